// round 3
// baseline (speedup 1.0000x reference)
#include <cuda_runtime.h>
#include <cstdint>
#include <cstddef>
#include <math.h>

#define B_TOTAL 512
#define T_LEN   256
#define HID     128
#define G4      512
#define WINDOW  8
#define ENCO    128
#define R_ROWS  4
#define NCTA    128
#define NTHR    512
#define K4_SM   24          // k-quads (4 floats = 2 pairs) in smem  -> k 0..95
#define K_TAIL_PAIRS 16     // k-pairs 48..63 (k 96..127) in registers
#define BT      (B_TOTAL * T_LEN)

typedef unsigned long long ull;

__device__ __forceinline__ ull ffma2(ull a, ull b, ull c) {
    ull d;
    asm("fma.rn.f32x2 %0, %1, %2, %3;" : "=l"(d) : "l"(a), "l"(b), "l"(c));
    return d;
}
__device__ __forceinline__ float lo32(ull v) { return __uint_as_float((unsigned)v); }
__device__ __forceinline__ float hi32(ull v) { return __uint_as_float((unsigned)(v >> 32)); }
__device__ __forceinline__ ull pack2(float a, float b) {
    return (ull)__float_as_uint(a) | ((ull)__float_as_uint(b) << 32);
}
// fast sigmoid / tanh (MUFU-based, rel err ~2e-6)
__device__ __forceinline__ float sigf(float x) {
    return __fdividef(1.f, 1.f + __expf(-x));
}
__device__ __forceinline__ float tanhf_(float x) {
    return 1.f - __fdividef(2.f, 1.f + __expf(2.f * x));
}

struct Smem {
    ull   Wq[K4_SM][G4][2];       // 196608 B : W_hh, 2 k-pairs per thread-col, LDS.128-able
    alignas(16) ull h2[R_ROWS][HID/2];  // 2048 B : hidden state as packed pairs
    float g[R_ROWS][G4];          //   8192 B : gate pre-activations (init staging too)
    float wih[5][G4];             //  10240 B
    float btot[G4];               //   2048 B
    float tout[R_ROWS][T_LEN];    //   4096 B
    float intv[R_ROWS][T_LEN];    //   4096 B
    float xv[R_ROWS][WINDOW][5];  //    640 B
    float fc1b[HID];              //    512 B
    float fc2w[HID];              //    512 B
    float Esm[R_ROWS];            //     16 B
    float red[R_ROWS][4];         //     64 B
};

// fc1 weights as transposed pairs: g_fc1p[k2*HID + u] = pack(fc1_w[u][2k2], fc1_w[u][2k2+1])
__device__ ull g_fc1p[64 * HID];

__global__ void prep_fc1(const float* __restrict__ fc1_w) {
    int idx = blockIdx.x * blockDim.x + threadIdx.x;
    if (idx < 64 * HID) {
        int k2 = idx >> 7, u = idx & 127;
        g_fc1p[idx] = pack2(fc1_w[u * HID + 2 * k2], fc1_w[u * HID + 2 * k2 + 1]);
    }
}

__global__ __launch_bounds__(NTHR, 1)
void modnn_kernel(const float* __restrict__ X,
                  const float* __restrict__ W_ih, const float* __restrict__ W_hh,
                  const float* __restrict__ b_ih, const float* __restrict__ b_hh,
                  const float* __restrict__ fc1_b,
                  const float* __restrict__ fc2_w, const float* __restrict__ fc2_b,
                  const float* __restrict__ int1_w, const float* __restrict__ int1_b,
                  const float* __restrict__ int3_w, const float* __restrict__ int3_b,
                  const float* __restrict__ scale_w, const float* __restrict__ zone_w,
                  float* __restrict__ out)
{
    extern __shared__ char smem_raw[];
    Smem* s = reinterpret_cast<Smem*>(smem_raw);
    const int tid = threadIdx.x;
    const int b0  = blockIdx.x * R_ROWS;

    // ---- stage W_hh k=0..95 as [k4][o][2] packed pairs ----
    for (int idx = tid; idx < K4_SM * G4; idx += NTHR) {
        int k4 = idx >> 9, o = idx & 511;
        const float* wr = W_hh + (size_t)o * HID + 4 * k4;
        s->Wq[k4][o][0] = pack2(wr[0], wr[1]);
        s->Wq[k4][o][1] = pack2(wr[2], wr[3]);
    }
    for (int idx = tid; idx < 5 * G4; idx += NTHR) {
        int j = idx >> 9, o = idx & 511;
        s->wih[j][o] = W_ih[o * 5 + j];
    }
    for (int idx = tid; idx < G4; idx += NTHR)
        s->btot[idx] = b_ih[idx] + b_hh[idx];
    if (tid < HID) { s->fc1b[tid] = fc1_b[tid]; s->fc2w[tid] = fc2_w[tid]; }

    // stage int-module weights into g area (reused later)
    {
        float* tmp = &s->g[0][0];   // [0:384)=int1_w, [384:512)=int1_b, [512:640)=int3_w
        for (int idx = tid; idx < HID * 3; idx += NTHR) tmp[idx] = int1_w[idx];
        for (int idx = tid; idx < HID; idx += NTHR) {
            tmp[384 + idx] = int1_b[idx];
            tmp[512 + idx] = int3_w[idx];
        }
    }

    // ---- W_hh tail (k-pairs 48..63) in registers: column o = tid ----
    ull wt[K_TAIL_PAIRS];
    {
        const ull* p = reinterpret_cast<const ull*>(W_hh + (size_t)tid * HID + 96);
        #pragma unroll
        for (int j = 0; j < K_TAIL_PAIRS; ++j) wt[j] = p[j];
    }

    const float zone = zone_w[0];
    const float fcb2 = fc2_b[0];
    const float i3b  = int3_b[0];
    const float scl  = scale_w[0];
    __syncthreads();

    // ---- precompute int_all; emit constant outputs; init tout/h/Esm ----
    {
        const float* tmp = &s->g[0][0];
        for (int it = tid; it < R_ROWS * T_LEN; it += NTHR) {
            int r = it >> 8, tt = it & 255;
            const float* Xb = X + (size_t)(b0 + r) * (T_LEN * 7) + tt * 7;
            float x0 = Xb[3], x1 = Xb[4], x2 = Xb[5];
            float acc = 0.f;
            #pragma unroll 8
            for (int u = 0; u < HID; ++u) {
                float v = fmaf(tmp[u*3], x0, fmaf(tmp[u*3+1], x1, fmaf(tmp[u*3+2], x2, tmp[384+u])));
                v = fmaxf(v, 0.f);
                acc = fmaf(v, tmp[512 + u], acc);
            }
            float val = scl * (1.f / (1.f + expf(-(acc + i3b))));   // accurate path (once)
            s->intv[r][tt] = val;
            size_t base = (size_t)(b0 + r) * T_LEN + tt;
            out[(size_t)BT + base]   = Xb[6];                          // HVAC_list
            out[3*(size_t)BT + base] = (tt >= WINDOW) ? val : 0.f;     // Int_list
            if (tt < WINDOW) {
                out[base]                = Xb[0];                      // TOut[:, :w] = T0
                out[2*(size_t)BT + base] = 0.f;                        // Ext_list zeros
                s->tout[r][tt] = Xb[0];
            }
        }
        for (int idx = tid; idx < R_ROWS * (HID/2); idx += NTHR)
            s->h2[idx >> 6][idx & 63] = pack2(1.f, 1.f);
        if (tid < R_ROWS)
            s->Esm[tid] = X[(size_t)(b0 + tid) * (T_LEN * 7) + WINDOW * 7];  // T0[:, 8]
    }
    __syncthreads();

    // ---- per-thread loop-invariants ----
    float wih_r[5];
    #pragma unroll
    for (int j = 0; j < 5; ++j) wih_r[j] = s->wih[j][tid];
    const float btot_r = s->btot[tid];
    const int rA = tid >> 7;       // phase-2 / fc1 row
    const int uu = tid & 127;
    float cst = 1.f;               // cell state for (rA, uu)

    // ================= main sequential time loop =================
    for (int i = WINDOW; i < T_LEN; ++i) {
        const bool  enc   = (i < ENCO);
        const float ratio = enc ? (float)i * (1.f / ENCO) : 0.f;

        // ---- window build: TOut[:, i] = E(old); embed inputs ----
        if (tid < R_ROWS * WINDOW) {
            int r = tid >> 3, tt = tid & 7;
            int pos = i - (WINDOW - 1) + tt;
            const float* Xb = X + (size_t)(b0 + r) * (T_LEN * 7);
            float TO;
            if (tt == WINDOW - 1) {
                TO = s->Esm[r];
                s->tout[r][i] = TO;
                out[(size_t)(b0 + r) * T_LEN + i] = TO;
            } else {
                TO = s->tout[r][pos];
            }
            float e0 = enc ? fmaf(Xb[pos * 7], ratio, TO * (1.f - ratio)) : TO;
            s->xv[r][tt][0] = e0;
            #pragma unroll
            for (int j = 1; j < 5; ++j) s->xv[r][tt][j] = Xb[pos * 7 + j];
        }
        __syncthreads();

        // ---- 8 LSTM sub-steps ----
        #pragma unroll 1
        for (int st = 0; st < WINDOW; ++st) {
            // phase 1: gate pre-activation for column o = tid, rows 0..3
            float v0 = btot_r, v1 = btot_r, v2 = btot_r, v3 = btot_r;
            #pragma unroll
            for (int j = 0; j < 5; ++j) {
                v0 = fmaf(s->xv[0][st][j], wih_r[j], v0);
                v1 = fmaf(s->xv[1][st][j], wih_r[j], v1);
                v2 = fmaf(s->xv[2][st][j], wih_r[j], v2);
                v3 = fmaf(s->xv[3][st][j], wih_r[j], v3);
            }
            ull a0 = 0, a1 = 0, a2 = 0, a3 = 0;
            const ulonglong2* hq0 = reinterpret_cast<const ulonglong2*>(s->h2[0]);
            const ulonglong2* hq1 = reinterpret_cast<const ulonglong2*>(s->h2[1]);
            const ulonglong2* hq2 = reinterpret_cast<const ulonglong2*>(s->h2[2]);
            const ulonglong2* hq3 = reinterpret_cast<const ulonglong2*>(s->h2[3]);
            #pragma unroll 6
            for (int k4 = 0; k4 < K4_SM; ++k4) {
                ulonglong2 w = *reinterpret_cast<const ulonglong2*>(&s->Wq[k4][tid][0]);
                ulonglong2 h0 = hq0[k4], h1 = hq1[k4], h2 = hq2[k4], h3 = hq3[k4];
                a0 = ffma2(w.x, h0.x, a0);  a0 = ffma2(w.y, h0.y, a0);
                a1 = ffma2(w.x, h1.x, a1);  a1 = ffma2(w.y, h1.y, a1);
                a2 = ffma2(w.x, h2.x, a2);  a2 = ffma2(w.y, h2.y, a2);
                a3 = ffma2(w.x, h3.x, a3);  a3 = ffma2(w.y, h3.y, a3);
            }
            #pragma unroll
            for (int j2 = 0; j2 < K_TAIL_PAIRS / 2; ++j2) {
                ulonglong2 h0 = hq0[K4_SM + j2], h1 = hq1[K4_SM + j2];
                ulonglong2 h2 = hq2[K4_SM + j2], h3 = hq3[K4_SM + j2];
                ull w0 = wt[2 * j2], w1 = wt[2 * j2 + 1];
                a0 = ffma2(w0, h0.x, a0);  a0 = ffma2(w1, h0.y, a0);
                a1 = ffma2(w0, h1.x, a1);  a1 = ffma2(w1, h1.y, a1);
                a2 = ffma2(w0, h2.x, a2);  a2 = ffma2(w1, h2.y, a2);
                a3 = ffma2(w0, h3.x, a3);  a3 = ffma2(w1, h3.y, a3);
            }
            s->g[0][tid] = v0 + lo32(a0) + hi32(a0);
            s->g[1][tid] = v1 + lo32(a1) + hi32(a1);
            s->g[2][tid] = v2 + lo32(a2) + hi32(a2);
            s->g[3][tid] = v3 + lo32(a3) + hi32(a3);
            __syncthreads();

            // phase 2: c/h update, one (row, unit) per thread
            {
                float gi = s->g[rA][uu],       gf = s->g[rA][uu + 128];
                float gg = s->g[rA][uu + 256], go = s->g[rA][uu + 384];
                cst = sigf(gf) * cst + sigf(gi) * tanhf_(gg);
                float hv = sigf(go) * tanhf_(cst);
                reinterpret_cast<float*>(&s->h2[0][0])[rA * HID + uu] = hv;
            }
            __syncthreads();
        }

        // ---- ext head: o = relu(fc1 h + b); ext = o . fc2_w + b2 ----
        {
            const ull* hA = s->h2[rA];
            ull A = 0;
            #pragma unroll 8
            for (int k2 = 0; k2 < 64; ++k2)
                A = ffma2(__ldg(&g_fc1p[k2 * HID + uu]), hA[k2], A);
            float p = fmaxf(lo32(A) + hi32(A) + s->fc1b[uu], 0.f) * s->fc2w[uu];
            #pragma unroll
            for (int m = 16; m > 0; m >>= 1)
                p += __shfl_xor_sync(0xFFFFFFFFu, p, m);
            if ((tid & 31) == 0)
                s->red[rA][(tid >> 5) & 3] = p;
        }
        __syncthreads();

        // ---- scalar tail: ext, total, E update (one thread per row) ----
        if (tid < R_ROWS) {
            int r = tid;
            float dot = s->red[r][0] + s->red[r][1] + s->red[r][2] + s->red[r][3];
            float ext = dot + fcb2;
            const float* Xb = X + (size_t)(b0 + r) * (T_LEN * 7);
            float hv = Xb[i * 7 + 6];
            float it = s->intv[r][i];
            float total = ext + hv + it;
            out[2*(size_t)BT + (size_t)(b0 + r) * T_LEN + i] = ext;
            float E = s->Esm[r];
            if (enc) E = ratio * Xb[i * 7] + (1.f - ratio) * E + total * zone;
            else     E = total * zone + E;
            s->Esm[r] = E;
        }
        __syncthreads();
    }
}

extern "C" void kernel_launch(void* const* d_in, const int* in_sizes, int n_in,
                              void* d_out, int out_size) {
    const float* X       = (const float*)d_in[0];
    const float* W_ih    = (const float*)d_in[1];
    const float* W_hh    = (const float*)d_in[2];
    const float* b_ih    = (const float*)d_in[3];
    const float* b_hh    = (const float*)d_in[4];
    const float* fc1_w   = (const float*)d_in[5];
    const float* fc1_b   = (const float*)d_in[6];
    const float* fc2_w   = (const float*)d_in[7];
    const float* fc2_b   = (const float*)d_in[8];
    const float* int1_w  = (const float*)d_in[9];
    const float* int1_b  = (const float*)d_in[10];
    const float* int3_w  = (const float*)d_in[11];
    const float* int3_b  = (const float*)d_in[12];
    const float* scale_w = (const float*)d_in[13];
    const float* zone_w  = (const float*)d_in[14];
    float* out = (float*)d_out;

    prep_fc1<<<64, 128>>>(fc1_w);

    size_t smem = sizeof(Smem);
    cudaFuncSetAttribute(modnn_kernel, cudaFuncAttributeMaxDynamicSharedMemorySize, (int)smem);
    modnn_kernel<<<NCTA, NTHR, smem>>>(X, W_ih, W_hh, b_ih, b_hh,
                                       fc1_b, fc2_w, fc2_b,
                                       int1_w, int1_b, int3_w, int3_b,
                                       scale_w, zone_w, out);
}